// round 2
// baseline (speedup 1.0000x reference)
#include <cuda_runtime.h>
#include <cstdint>
#include <math.h>

#define NT 512
#define TILE 64
#define BSTRIDE 7296          // floats per B double-buffer half (16*456 max chunk)
#define G_OFF    25344        // seg1 size: 192*132 floats
#define B_OFF    37888        // G size: 64*196 = 12544 floats
#define SMEM_FLOATS 52480     // + 2*7296 B buffer

static __device__ __forceinline__ float f2tff(float f){
  uint32_t u; asm("cvt.rna.tf32.f32 %0, %1;" : "=r"(u) : "f"(f));
  return __uint_as_float(u);
}

static __device__ __forceinline__ void mma8(float* d, uint32_t a0, uint32_t a1,
                                            uint32_t a2, uint32_t a3,
                                            uint32_t b0, uint32_t b1){
  asm volatile("mma.sync.aligned.m16n8k8.row.col.f32.tf32.tf32.f32 "
      "{%0,%1,%2,%3}, {%4,%5,%6,%7}, {%8,%9}, {%0,%1,%2,%3};"
      : "+f"(d[0]), "+f"(d[1]), "+f"(d[2]), "+f"(d[3])
      : "r"(a0), "r"(a1), "r"(a2), "r"(a3), "r"(b0), "r"(b1));
}

// C += A(SMEM tf32, pitch PA) @ B(global fp32 KxN row-major), K chunked by 16.
// B is converted to tf32 and double-buffered through SMEM. Warp grid fixed 4x4.
template<int K, int N, int PB, int WM, int WN, int PA>
static __device__ __forceinline__ void run_gemm(const float* __restrict__ gB,
                  const float* __restrict__ As, float* __restrict__ Bbuf,
                  float* acc, int tid, int lane, int mi, int nj)
{
  constexpr int NKC = K/16;
  constexpr int V4  = (16*N)/4;
  constexpr int NLB = (V4 + NT - 1)/NT;
  float4 lb[NLB];

  #pragma unroll
  for (int i=0;i<NLB;i++){ int t=tid+i*NT;
    if (t<V4) lb[i] = reinterpret_cast<const float4*>(gB)[t]; }
  __syncthreads();   // prior consumers of Bbuf / producers of As are done
  #pragma unroll
  for (int i=0;i<NLB;i++){ int t=tid+i*NT;
    if (t<V4){ int e=t*4; int k=e/N; int n=e-k*N; float4 v=lb[i];
      *reinterpret_cast<float4*>(Bbuf + k*PB + n) =
        make_float4(f2tff(v.x),f2tff(v.y),f2tff(v.z),f2tff(v.w)); } }
  __syncthreads();

  for (int kc=0; kc<NKC; kc++){
    if (kc+1 < NKC){
      const float4* src = reinterpret_cast<const float4*>(gB + (kc+1)*16*N);
      #pragma unroll
      for (int i=0;i<NLB;i++){ int t=tid+i*NT; if (t<V4) lb[i]=src[t]; }
    }
    const float* bb = Bbuf + (kc&1)*BSTRIDE;
    #pragma unroll
    for (int s=0; s<2; s++){
      const int kb = s*8;
      uint32_t af[WM][4];
      #pragma unroll
      for (int wm=0; wm<WM; wm++){
        const float* ap = As + ((mi*WM+wm)*16 + (lane>>2))*PA + kc*16 + kb + (lane&3);
        af[wm][0] = __float_as_uint(ap[0]);
        af[wm][1] = __float_as_uint(ap[8*PA]);
        af[wm][2] = __float_as_uint(ap[4]);
        af[wm][3] = __float_as_uint(ap[8*PA+4]);
      }
      #pragma unroll
      for (int wn=0; wn<WN; wn++){
        const float* bp = bb + (kb + (lane&3))*PB + (nj*WN+wn)*8 + (lane>>2);
        uint32_t b0 = __float_as_uint(bp[0]);
        uint32_t b1 = __float_as_uint(bp[4*PB]);
        #pragma unroll
        for (int wm=0; wm<WM; wm++)
          mma8(acc + (wm*WN+wn)*4, af[wm][0],af[wm][1],af[wm][2],af[wm][3], b0, b1);
      }
    }
    __syncthreads();   // all warps done reading this chunk (and the other half)
    if (kc+1 < NKC){
      #pragma unroll
      for (int i=0;i<NLB;i++){ int t=tid+i*NT;
        if (t<V4){ int e=t*4; int k=e/N; int n=e-k*N; float4 v=lb[i];
          *reinterpret_cast<float4*>(Bbuf + ((kc+1)&1)*BSTRIDE + k*PB + n) =
            make_float4(f2tff(v.x),f2tff(v.y),f2tff(v.z),f2tff(v.w)); } }
      __syncthreads();
    }
  }
}

static __device__ __forceinline__ float sspf(float v, float cssp){
  // C * (softplus(v) - ln2)
  float sp = fmaxf(v, 0.0f) + log1pf(expf(-fabsf(v)));
  return cssp * (sp - 0.69314718055994531f);
}

__global__ void __launch_bounds__(NT, 1)
resblk_kernel(const float* __restrict__ x,
              const float* __restrict__ w1s,  const float* __restrict__ w1v1,
              const float* __restrict__ w1v2, const float* __restrict__ w2s,
              const float* __restrict__ w2v1, const float* __restrict__ w2v2,
              float* __restrict__ out, float cssp)
{
  extern __shared__ float sm[];
  float* seg1 = sm;
  float* G    = sm + G_OFF;
  float* Bbuf = sm + B_OFF;

  const int tid  = threadIdx.x;
  const int lane = tid & 31;
  const int warp = tid >> 5;
  const int mi   = warp >> 2;     // 0..3  (M direction)
  const int nj   = warp & 3;      // 0..3  (N direction)
  const int n0   = blockIdx.x * TILE;
  const float RS128 = 0.08838834764831845f;  // 1/sqrt(128)
  const float RS64  = 0.125f;                // 1/sqrt(64)

  // ================= scalar path =================
  // A0 = tf32(x0 tile)  [64 x 256], pitch 260
  for (int t=tid; t<(TILE*256)/4; t+=NT){
    int e=t*4; int ln=e>>8; int col=e&255;
    float4 v = *reinterpret_cast<const float4*>(x + (size_t)(n0+ln)*960 + col);
    *reinterpret_cast<float4*>(seg1 + ln*260 + col) =
      make_float4(f2tff(v.x),f2tff(v.y),f2tff(v.z),f2tff(v.w));
  }
  // s = A0 @ w1s / 16, then SSP -> scalars(seg1, tf32) + gates(G, fp32)
  {
    float acc[56];
    #pragma unroll
    for (int i=0;i<56;i++) acc[i]=0.f;
    run_gemm<256,448,456,1,14,260>(w1s, seg1, Bbuf, acc, tid, lane, mi, nj);
    #pragma unroll
    for (int wn=0; wn<14; wn++){
      #pragma unroll
      for (int q=0;q<4;q++){
        int row = mi*16 + (lane>>2) + ((q&2)<<2);
        int col = (nj*14+wn)*8 + ((lane&3)<<1) + (q&1);
        float h = sspf(acc[wn*4+q]*0.0625f, cssp);
        if (col < 256) seg1[row*260 + col] = f2tff(h);
        else           G[row*196 + (col-256)] = h;
      }
    }
  }
  // y0 = scalars @ w2s / 16 ; stage in seg1 then coalesced residual write
  {
    float acc[32];
    #pragma unroll
    for (int i=0;i<32;i++) acc[i]=0.f;
    run_gemm<256,256,264,1,8,260>(w2s, seg1, Bbuf, acc, tid, lane, mi, nj);
    #pragma unroll
    for (int wn=0; wn<8; wn++){
      #pragma unroll
      for (int q=0;q<4;q++){
        int row = mi*16 + (lane>>2) + ((q&2)<<2);
        int col = (nj*8+wn)*8 + ((lane&3)<<1) + (q&1);
        seg1[row*260 + col] = acc[wn*4+q]*0.0625f;
      }
    }
    __syncthreads();
    for (int t=tid; t<TILE*64; t+=NT){            // 64 rows x 64 float4
      int ln=t>>6; int j=(t&63)*4;
      size_t off = (size_t)(n0+ln)*960 + j;
      float4 xr = *reinterpret_cast<const float4*>(x + off);
      float4 yv = *reinterpret_cast<const float4*>(seg1 + ln*260 + j);
      *reinterpret_cast<float4*>(out + off) =
        make_float4(xr.x+yv.x, xr.y+yv.y, xr.z+yv.z, xr.w+yv.w);
    }
  }
  __syncthreads();

  // ================= v1 path =================
  // A1[c*64+n][i] = tf32(x[n, 256+3i+c])  [192 x 128], pitch 132
  for (int t=tid; t<(TILE*384)/4; t+=NT){
    int e=t*4; int ln=e/384; int j=e-ln*384;
    float4 v = *reinterpret_cast<const float4*>(x + (size_t)(n0+ln)*960 + 256 + j);
    float vv[4]={v.x,v.y,v.z,v.w};
    #pragma unroll
    for (int q=0;q<4;q++){
      int jj=j+q; int i3=jj/3; int c=jj-i3*3;
      seg1[(c*64+ln)*132 + i3] = f2tff(vv[q]);
    }
  }
  // V1 = A1 @ w1v1 * rs128, gated, in-place (tf32)
  {
    float acc[48];
    #pragma unroll
    for (int i=0;i<48;i++) acc[i]=0.f;
    run_gemm<128,128,136,3,4,132>(w1v1, seg1, Bbuf, acc, tid, lane, mi, nj);
    #pragma unroll
    for (int wm=0; wm<3; wm++){
      #pragma unroll
      for (int wn=0; wn<4; wn++){
        #pragma unroll
        for (int q=0;q<4;q++){
          int row = (mi*3+wm)*16 + (lane>>2) + ((q&2)<<2);
          int col = (nj*4+wn)*8 + ((lane&3)<<1) + (q&1);
          float g = G[(row&63)*196 + col];
          seg1[row*132 + col] = f2tff(acc[(wm*4+wn)*4+q]*RS128*g);
        }
      }
    }
  }
  // Y1 = V1 @ w2v1 * rs128 -> stage [n][3o+c] -> coalesced residual write
  {
    float acc[48];
    #pragma unroll
    for (int i=0;i<48;i++) acc[i]=0.f;
    run_gemm<128,128,136,3,4,132>(w2v1, seg1, Bbuf, acc, tid, lane, mi, nj);
    #pragma unroll
    for (int wm=0; wm<3; wm++){
      #pragma unroll
      for (int wn=0; wn<4; wn++){
        #pragma unroll
        for (int q=0;q<4;q++){
          int row = (mi*3+wm)*16 + (lane>>2) + ((q&2)<<2);
          int col = (nj*4+wn)*8 + ((lane&3)<<1) + (q&1);
          int n = row & 63; int c = row >> 6;
          seg1[n*388 + 3*col + c] = acc[(wm*4+wn)*4+q]*RS128;
        }
      }
    }
    __syncthreads();
    for (int t=tid; t<TILE*96; t+=NT){            // 64 rows x 96 float4
      int ln=t/96; int j=(t-ln*96)*4;
      size_t off = (size_t)(n0+ln)*960 + 256 + j;
      float4 xr = *reinterpret_cast<const float4*>(x + off);
      float4 yv = *reinterpret_cast<const float4*>(seg1 + ln*388 + j);
      *reinterpret_cast<float4*>(out + off) =
        make_float4(xr.x+yv.x, xr.y+yv.y, xr.z+yv.z, xr.w+yv.w);
    }
  }
  __syncthreads();

  // ================= v2 path =================
  // A2[c*64+n][i] = tf32(x[n, 640+5i+c])  [320 x 64], pitch 68
  for (int t=tid; t<(TILE*320)/4; t+=NT){
    int e=t*4; int ln=e/320; int j=e-ln*320;
    float4 v = *reinterpret_cast<const float4*>(x + (size_t)(n0+ln)*960 + 640 + j);
    float vv[4]={v.x,v.y,v.z,v.w};
    #pragma unroll
    for (int q=0;q<4;q++){
      int jj=j+q; int i5=jj/5; int c=jj-i5*5;
      seg1[(c*64+ln)*68 + i5] = f2tff(vv[q]);
    }
  }
  // V2 = A2 @ w1v2 * rs64, gated, in-place (tf32)
  {
    float acc[40];
    #pragma unroll
    for (int i=0;i<40;i++) acc[i]=0.f;
    run_gemm<64,64,72,5,2,68>(w1v2, seg1, Bbuf, acc, tid, lane, mi, nj);
    #pragma unroll
    for (int wm=0; wm<5; wm++){
      #pragma unroll
      for (int wn=0; wn<2; wn++){
        #pragma unroll
        for (int q=0;q<4;q++){
          int row = (mi*5+wm)*16 + (lane>>2) + ((q&2)<<2);
          int col = (nj*2+wn)*8 + ((lane&3)<<1) + (q&1);
          float g = G[(row&63)*196 + 128 + col];
          seg1[row*68 + col] = f2tff(acc[(wm*2+wn)*4+q]*RS64*g);
        }
      }
    }
  }
  // Y2 = V2 @ w2v2 * rs64 -> stage [n][5o+c] -> coalesced residual write
  {
    float acc[40];
    #pragma unroll
    for (int i=0;i<40;i++) acc[i]=0.f;
    run_gemm<64,64,72,5,2,68>(w2v2, seg1, Bbuf, acc, tid, lane, mi, nj);
    #pragma unroll
    for (int wm=0; wm<5; wm++){
      #pragma unroll
      for (int wn=0; wn<2; wn++){
        #pragma unroll
        for (int q=0;q<4;q++){
          int row = (mi*5+wm)*16 + (lane>>2) + ((q&2)<<2);
          int col = (nj*2+wn)*8 + ((lane&3)<<1) + (q&1);
          int n = row & 63; int c = row >> 6;
          seg1[n*324 + 5*col + c] = acc[(wm*2+wn)*4+q]*RS64;
        }
      }
    }
    __syncthreads();
    for (int t=tid; t<TILE*80; t+=NT){            // 64 rows x 80 float4
      int ln=t/80; int j=(t-ln*80)*4;
      size_t off = (size_t)(n0+ln)*960 + 640 + j;
      float4 xr = *reinterpret_cast<const float4*>(x + off);
      float4 yv = *reinterpret_cast<const float4*>(seg1 + ln*324 + j);
      *reinterpret_cast<float4*>(out + off) =
        make_float4(xr.x+yv.x, xr.y+yv.y, xr.z+yv.z, xr.w+yv.w);
    }
  }
}

static double compute_cssp_host(){
  const int NP = 200001;
  const double LOG2 = 0.6931471805599453094172321214581766;
  double s = 0.0;
  for (int i=0;i<NP;i++){
    double z = -10.0 + (20.0 * i) / (NP - 1);
    double phi = exp(-0.5*z*z) / sqrt(2.0*3.14159265358979323846);
    double sp  = (z > 0.0) ? (z + log1p(exp(-z))) : log1p(exp(z));
    double f   = sp - LOG2;
    double w   = (i==0 || i==NP-1) ? 0.5 : 1.0;
    s += w * f * f * phi;
  }
  s *= 20.0 / (NP - 1);
  return 1.0 / sqrt(s);
}

extern "C" void kernel_launch(void* const* d_in, const int* in_sizes, int n_in,
                              void* d_out, int out_size) {
  const float* x    = (const float*)d_in[0];
  const float* w1s  = (const float*)d_in[1];
  const float* w1v1 = (const float*)d_in[2];
  const float* w1v2 = (const float*)d_in[3];
  const float* w2s  = (const float*)d_in[4];
  const float* w2v1 = (const float*)d_in[5];
  const float* w2v2 = (const float*)d_in[6];
  float* out = (float*)d_out;

  int n = in_sizes[0] / 960;

  static bool attr_done = false;
  if (!attr_done){
    cudaFuncSetAttribute(resblk_kernel,
        cudaFuncAttributeMaxDynamicSharedMemorySize, SMEM_FLOATS*4);
    attr_done = true;
  }
  static const float cssp = (float)compute_cssp_host();

  resblk_kernel<<<n/TILE, NT, SMEM_FLOATS*4>>>(
      x, w1s, w1v1, w1v2, w2s, w2v1, w2v2, out, cssp);
}

// round 3
// speedup vs baseline: 1.0130x; 1.0130x over previous
#include <cuda_runtime.h>
#include <cstdint>
#include <math.h>

#define NT 512
#define TILE 64
#define BSTRIDE 7168          // floats per B buffer half (16*448 max chunk)
#define G_OFF    25344        // seg1 size: 192*132 floats
#define B_OFF    37888        // G size: 64*196 = 12544 floats
#define SMEM_FLOATS 52224     // + 2*7168 B buffer  (208896 bytes)

// Pre-converted, pre-permuted tf32 weights (filled by prep_weights each launch)
#define W1S_OFF   0
#define W2S_OFF   114688
#define W1V1_OFF  180224
#define W2V1_OFF  196608
#define W1V2_OFF  212992
#define W2V2_OFF  217088
#define WBUF_SZ   221184
__device__ float WBUF[WBUF_SZ];

static __device__ __forceinline__ float f2tff(float f){
  uint32_t u; asm("cvt.rna.tf32.f32 %0, %1;" : "=r"(u) : "f"(f));
  return __uint_as_float(u);
}

static __device__ __forceinline__ void mma8(float* d, uint32_t a0, uint32_t a1,
                                            uint32_t a2, uint32_t a3,
                                            uint32_t b0, uint32_t b1){
  asm volatile("mma.sync.aligned.m16n8k8.row.col.f32.tf32.tf32.f32 "
      "{%0,%1,%2,%3}, {%4,%5,%6,%7}, {%8,%9}, {%0,%1,%2,%3};"
      : "+f"(d[0]), "+f"(d[1]), "+f"(d[2]), "+f"(d[3])
      : "r"(a0), "r"(a1), "r"(a2), "r"(a3), "r"(b0), "r"(b1));
}

static __device__ __forceinline__ void cpa16(uint32_t s, const void* g){
  asm volatile("cp.async.ca.shared.global [%0], [%1], 16;" :: "r"(s), "l"(g));
}
static __device__ __forceinline__ void cpa_commit(){
  asm volatile("cp.async.commit_group;");
}
static __device__ __forceinline__ void cpa_wait0(){
  asm volatile("cp.async.wait_group 0;");
}

// ---------------------------------------------------------------------------
// Init kernel: convert weights to tf32 and permute into chunked N-major layout.
// For each K=16 chunk kc of a KxN weight W:
//   WBUF[off + kc*N*16 + n*16 + w] = tf32( W[(kc*16 + (w&3)*4 + (w>>2)) * N + n] )
// so that an LDS.128 at [n*16 + p*4] yields k = {p, p+4, p+8, p+12} (both k8 steps).
// ---------------------------------------------------------------------------
__global__ void prep_weights(const float* __restrict__ w1s,
                             const float* __restrict__ w1v1,
                             const float* __restrict__ w1v2,
                             const float* __restrict__ w2s,
                             const float* __restrict__ w2v1,
                             const float* __restrict__ w2v2)
{
  int idx = blockIdx.x * blockDim.x + threadIdx.x;
  if (idx >= WBUF_SZ) return;
  const float* src; int N, loc;
  if      (idx < W2S_OFF)  { src = w1s;  N = 448; loc = idx - W1S_OFF;  }
  else if (idx < W1V1_OFF) { src = w2s;  N = 256; loc = idx - W2S_OFF;  }
  else if (idx < W2V1_OFF) { src = w1v1; N = 128; loc = idx - W1V1_OFF; }
  else if (idx < W1V2_OFF) { src = w2v1; N = 128; loc = idx - W2V1_OFF; }
  else if (idx < W2V2_OFF) { src = w1v2; N = 64;  loc = idx - W1V2_OFF; }
  else                     { src = w2v2; N = 64;  loc = idx - W2V2_OFF; }
  int kc = loc / (N*16); int r = loc - kc*N*16; int n = r >> 4; int w = r & 15;
  int k = kc*16 + (w&3)*4 + (w>>2);
  WBUF[idx] = f2tff(src[k*N + n]);
}

// ---------------------------------------------------------------------------
// C += A(SMEM tf32, plain pitch PA) @ B(WBUF permuted chunks), K chunked by 16.
// cp.async double-buffers B chunks; 1 syncthreads + 1 wait per chunk.
// Warp grid fixed 4(M) x 4(N).
// ---------------------------------------------------------------------------
template<int K, int N, int WM, int WN, int PA>
static __device__ __forceinline__ void run_gemm(const float* __restrict__ gB,
                  const float* __restrict__ As, const float* __restrict__ Bsm,
                  uint32_t Bsm_u32, float* acc, int tid, int lane, int mi, int nj)
{
  constexpr int NKC = K/16;
  constexpr int CHF = N*16;       // floats per chunk
  constexpr int CHB = CHF*4;      // bytes per chunk

  // prologue: chunk 0 -> buf 0
  {
    const char* src = (const char*)gB;
    for (int b = tid*16; b < CHB; b += NT*16) cpa16(Bsm_u32 + b, src + b);
    cpa_commit();
    cpa_wait0();
  }
  __syncthreads();

  for (int kc=0; kc<NKC; kc++){
    if (kc+1 < NKC){
      const char* src = (const char*)(gB + (size_t)(kc+1)*CHF);
      uint32_t dst = Bsm_u32 + ((kc+1)&1)*(BSTRIDE*4);
      for (int b = tid*16; b < CHB; b += NT*16) cpa16(dst + b, src + b);
      cpa_commit();
    }
    const float* bb = Bsm + (kc&1)*BSTRIDE;

    uint32_t af[WM][2][4];
    #pragma unroll
    for (int wm=0; wm<WM; wm++){
      const float* ap = As + ((mi*WM+wm)*16 + (lane>>2))*PA + kc*16 + (lane&3);
      #pragma unroll
      for (int s=0; s<2; s++){
        af[wm][s][0] = __float_as_uint(ap[s*8]);
        af[wm][s][1] = __float_as_uint(ap[s*8 + 8*PA]);
        af[wm][s][2] = __float_as_uint(ap[s*8 + 4]);
        af[wm][s][3] = __float_as_uint(ap[s*8 + 8*PA + 4]);
      }
    }
    #pragma unroll
    for (int wn=0; wn<WN; wn++){
      int col = (nj*WN+wn)*8 + (lane>>2);
      float4 b = *reinterpret_cast<const float4*>(bb + col*16 + (lane&3)*4);
      #pragma unroll
      for (int wm=0; wm<WM; wm++){
        mma8(acc+(wm*WN+wn)*4, af[wm][0][0],af[wm][0][1],af[wm][0][2],af[wm][0][3],
             __float_as_uint(b.x), __float_as_uint(b.y));
        mma8(acc+(wm*WN+wn)*4, af[wm][1][0],af[wm][1][1],af[wm][1][2],af[wm][1][3],
             __float_as_uint(b.z), __float_as_uint(b.w));
      }
    }
    if (kc+1 < NKC) cpa_wait0();
    __syncthreads();
  }
}

static __device__ __forceinline__ float sspf(float v, float cssp){
  float sp = fmaxf(v, 0.0f) + log1pf(expf(-fabsf(v)));
  return cssp * (sp - 0.69314718055994531f);
}

__global__ void __launch_bounds__(NT, 1)
resblk_kernel(const float* __restrict__ x, float* __restrict__ out, float cssp)
{
  extern __shared__ float sm[];
  float* seg1 = sm;
  float* G    = sm + G_OFF;
  float* Bsm  = sm + B_OFF;
  uint32_t sm_u32;
  { uint32_t a; asm("{ .reg .u64 t; cvta.to.shared.u64 t, %1; cvt.u32.u64 %0, t; }"
                    : "=r"(a) : "l"(sm)); sm_u32 = a; }
  const uint32_t Bsm_u32 = sm_u32 + B_OFF*4;

  const int tid  = threadIdx.x;
  const int lane = tid & 31;
  const int warp = tid >> 5;
  const int mi   = warp >> 2;
  const int nj   = warp & 3;
  const int n0   = blockIdx.x * TILE;
  const float RS128 = 0.08838834764831845f;
  const float RS64  = 0.125f;

  // ================= scalar path =================
  // A0 = tf32(x0 tile)  [64 x 256], pitch 260
  for (int t=tid; t<(TILE*256)/4; t+=NT){
    int e=t*4; int ln=e>>8; int col=e&255;
    float4 v = *reinterpret_cast<const float4*>(x + (size_t)(n0+ln)*960 + col);
    *reinterpret_cast<float4*>(seg1 + ln*260 + col) =
      make_float4(f2tff(v.x),f2tff(v.y),f2tff(v.z),f2tff(v.w));
  }
  // s = A0 @ w1s / 16, then SSP -> scalars(seg1, tf32) + gates(G, fp32)
  {
    float acc[56];
    #pragma unroll
    for (int i=0;i<56;i++) acc[i]=0.f;
    run_gemm<256,448,1,14,260>(WBUF+W1S_OFF, seg1, Bsm, Bsm_u32, acc, tid, lane, mi, nj);
    #pragma unroll
    for (int wn=0; wn<14; wn++){
      #pragma unroll
      for (int q=0;q<4;q++){
        int row = mi*16 + (lane>>2) + ((q&2)<<2);
        int col = (nj*14+wn)*8 + ((lane&3)<<1) + (q&1);
        float h = sspf(acc[wn*4+q]*0.0625f, cssp);
        if (col < 256) seg1[row*260 + col] = f2tff(h);
        else           G[row*196 + (col-256)] = h;
      }
    }
  }
  // y0 = scalars @ w2s / 16 ; stage in seg1 then coalesced residual write
  {
    float acc[32];
    #pragma unroll
    for (int i=0;i<32;i++) acc[i]=0.f;
    run_gemm<256,256,1,8,260>(WBUF+W2S_OFF, seg1, Bsm, Bsm_u32, acc, tid, lane, mi, nj);
    #pragma unroll
    for (int wn=0; wn<8; wn++){
      #pragma unroll
      for (int q=0;q<4;q++){
        int row = mi*16 + (lane>>2) + ((q&2)<<2);
        int col = (nj*8+wn)*8 + ((lane&3)<<1) + (q&1);
        seg1[row*260 + col] = acc[wn*4+q]*0.0625f;
      }
    }
    __syncthreads();
    for (int t=tid; t<TILE*64; t+=NT){
      int ln=t>>6; int j=(t&63)*4;
      size_t off = (size_t)(n0+ln)*960 + j;
      float4 xr = *reinterpret_cast<const float4*>(x + off);
      float4 yv = *reinterpret_cast<const float4*>(seg1 + ln*260 + j);
      *reinterpret_cast<float4*>(out + off) =
        make_float4(xr.x+yv.x, xr.y+yv.y, xr.z+yv.z, xr.w+yv.w);
    }
  }
  __syncthreads();

  // ================= v1 path =================
  // A1[c*64+n][i] = tf32(x[n, 256+3i+c])  [192 x 128], pitch 132
  for (int t=tid; t<(TILE*384)/4; t+=NT){
    int e=t*4; int ln=e/384; int j=e-ln*384;
    float4 v = *reinterpret_cast<const float4*>(x + (size_t)(n0+ln)*960 + 256 + j);
    float vv[4]={v.x,v.y,v.z,v.w};
    #pragma unroll
    for (int q=0;q<4;q++){
      int jj=j+q; int i3=jj/3; int c=jj-i3*3;
      seg1[(c*64+ln)*132 + i3] = f2tff(vv[q]);
    }
  }
  // V1 = A1 @ w1v1 * rs128, gated, in-place (tf32)
  {
    float acc[48];
    #pragma unroll
    for (int i=0;i<48;i++) acc[i]=0.f;
    run_gemm<128,128,3,4,132>(WBUF+W1V1_OFF, seg1, Bsm, Bsm_u32, acc, tid, lane, mi, nj);
    #pragma unroll
    for (int wm=0; wm<3; wm++){
      #pragma unroll
      for (int wn=0; wn<4; wn++){
        #pragma unroll
        for (int q=0;q<4;q++){
          int row = (mi*3+wm)*16 + (lane>>2) + ((q&2)<<2);
          int col = (nj*4+wn)*8 + ((lane&3)<<1) + (q&1);
          float g = G[(row&63)*196 + col];
          seg1[row*132 + col] = f2tff(acc[(wm*4+wn)*4+q]*RS128*g);
        }
      }
    }
  }
  // Y1 = V1 @ w2v1 * rs128 -> stage [n][3o+c] -> coalesced residual write
  {
    float acc[48];
    #pragma unroll
    for (int i=0;i<48;i++) acc[i]=0.f;
    run_gemm<128,128,3,4,132>(WBUF+W2V1_OFF, seg1, Bsm, Bsm_u32, acc, tid, lane, mi, nj);
    #pragma unroll
    for (int wm=0; wm<3; wm++){
      #pragma unroll
      for (int wn=0; wn<4; wn++){
        #pragma unroll
        for (int q=0;q<4;q++){
          int row = (mi*3+wm)*16 + (lane>>2) + ((q&2)<<2);
          int col = (nj*4+wn)*8 + ((lane&3)<<1) + (q&1);
          int n = row & 63; int c = row >> 6;
          seg1[n*388 + 3*col + c] = acc[(wm*4+wn)*4+q]*RS128;
        }
      }
    }
    __syncthreads();
    for (int t=tid; t<TILE*96; t+=NT){
      int ln=t/96; int j=(t-ln*96)*4;
      size_t off = (size_t)(n0+ln)*960 + 256 + j;
      float4 xr = *reinterpret_cast<const float4*>(x + off);
      float4 yv = *reinterpret_cast<const float4*>(seg1 + ln*388 + j);
      *reinterpret_cast<float4*>(out + off) =
        make_float4(xr.x+yv.x, xr.y+yv.y, xr.z+yv.z, xr.w+yv.w);
    }
  }
  __syncthreads();

  // ================= v2 path =================
  // A2[c*64+n][i] = tf32(x[n, 640+5i+c])  [320 x 64], pitch 68
  for (int t=tid; t<(TILE*320)/4; t+=NT){
    int e=t*4; int ln=e/320; int j=e-ln*320;
    float4 v = *reinterpret_cast<const float4*>(x + (size_t)(n0+ln)*960 + 640 + j);
    float vv[4]={v.x,v.y,v.z,v.w};
    #pragma unroll
    for (int q=0;q<4;q++){
      int jj=j+q; int i5=jj/5; int c=jj-i5*5;
      seg1[(c*64+ln)*68 + i5] = f2tff(vv[q]);
    }
  }
  // V2 = A2 @ w1v2 * rs64, gated, in-place (tf32)
  {
    float acc[40];
    #pragma unroll
    for (int i=0;i<40;i++) acc[i]=0.f;
    run_gemm<64,64,5,2,68>(WBUF+W1V2_OFF, seg1, Bsm, Bsm_u32, acc, tid, lane, mi, nj);
    #pragma unroll
    for (int wm=0; wm<5; wm++){
      #pragma unroll
      for (int wn=0; wn<2; wn++){
        #pragma unroll
        for (int q=0;q<4;q++){
          int row = (mi*5+wm)*16 + (lane>>2) + ((q&2)<<2);
          int col = (nj*2+wn)*8 + ((lane&3)<<1) + (q&1);
          float g = G[(row&63)*196 + 128 + col];
          seg1[row*68 + col] = f2tff(acc[(wm*2+wn)*4+q]*RS64*g);
        }
      }
    }
  }
  // Y2 = V2 @ w2v2 * rs64 -> stage [n][5o+c] -> coalesced residual write
  {
    float acc[40];
    #pragma unroll
    for (int i=0;i<40;i++) acc[i]=0.f;
    run_gemm<64,64,5,2,68>(WBUF+W2V2_OFF, seg1, Bsm, Bsm_u32, acc, tid, lane, mi, nj);
    #pragma unroll
    for (int wm=0; wm<5; wm++){
      #pragma unroll
      for (int wn=0; wn<2; wn++){
        #pragma unroll
        for (int q=0;q<4;q++){
          int row = (mi*5+wm)*16 + (lane>>2) + ((q&2)<<2);
          int col = (nj*2+wn)*8 + ((lane&3)<<1) + (q&1);
          int n = row & 63; int c = row >> 6;
          seg1[n*324 + 5*col + c] = acc[(wm*2+wn)*4+q]*RS64;
        }
      }
    }
    __syncthreads();
    for (int t=tid; t<TILE*80; t+=NT){
      int ln=t/80; int j=(t-ln*80)*4;
      size_t off = (size_t)(n0+ln)*960 + 640 + j;
      float4 xr = *reinterpret_cast<const float4*>(x + off);
      float4 yv = *reinterpret_cast<const float4*>(seg1 + ln*324 + j);
      *reinterpret_cast<float4*>(out + off) =
        make_float4(xr.x+yv.x, xr.y+yv.y, xr.z+yv.z, xr.w+yv.w);
    }
  }
}

static double compute_cssp_host(){
  const int NP = 200001;
  const double LOG2 = 0.6931471805599453094172321214581766;
  double s = 0.0;
  for (int i=0;i<NP;i++){
    double z = -10.0 + (20.0 * i) / (NP - 1);
    double phi = exp(-0.5*z*z) / sqrt(2.0*3.14159265358979323846);
    double sp  = (z > 0.0) ? (z + log1p(exp(-z))) : log1p(exp(z));
    double f   = sp - LOG2;
    double w   = (i==0 || i==NP-1) ? 0.5 : 1.0;
    s += w * f * f * phi;
  }
  s *= 20.0 / (NP - 1);
  return 1.0 / sqrt(s);
}

extern "C" void kernel_launch(void* const* d_in, const int* in_sizes, int n_in,
                              void* d_out, int out_size) {
  const float* x    = (const float*)d_in[0];
  const float* w1s  = (const float*)d_in[1];
  const float* w1v1 = (const float*)d_in[2];
  const float* w1v2 = (const float*)d_in[3];
  const float* w2s  = (const float*)d_in[4];
  const float* w2v1 = (const float*)d_in[5];
  const float* w2v2 = (const float*)d_in[6];
  float* out = (float*)d_out;

  int n = in_sizes[0] / 960;

  static bool attr_done = false;
  if (!attr_done){
    cudaFuncSetAttribute(resblk_kernel,
        cudaFuncAttributeMaxDynamicSharedMemorySize, SMEM_FLOATS*4);
    attr_done = true;
  }
  static const float cssp = (float)compute_cssp_host();

  prep_weights<<<(WBUF_SZ + NT - 1)/NT, NT>>>(w1s, w1v1, w1v2, w2s, w2v1, w2v2);
  resblk_kernel<<<n/TILE, NT, SMEM_FLOATS*4>>>(x, out, cssp);
}

// round 4
// speedup vs baseline: 1.2718x; 1.2555x over previous
#include <cuda_runtime.h>
#include <cstdint>
#include <math.h>

#define NT 512
#define TILE 64
#define G_OFF    25344        // seg1 size: 192*132 floats
#define SMEM_FLOATS 37888     // seg1 + G (64*196)   = 151552 bytes

// Pre-converted tf32 weights, permuted per-k8-chunk N-major (filled by prep_weights)
#define W1S_OFF   0
#define W2S_OFF   114688
#define W1V1_OFF  180224
#define W2V1_OFF  196608
#define W1V2_OFF  212992
#define W2V2_OFF  217088
#define WBUF_SZ   221184
__device__ float WBUF[WBUF_SZ];

static __device__ __forceinline__ float f2tff(float f){
  uint32_t u; asm("cvt.rna.tf32.f32 %0, %1;" : "=r"(u) : "f"(f));
  return __uint_as_float(u);
}

static __device__ __forceinline__ void mma8(float* d, uint32_t a0, uint32_t a1,
                                            uint32_t a2, uint32_t a3,
                                            uint32_t b0, uint32_t b1){
  asm volatile("mma.sync.aligned.m16n8k8.row.col.f32.tf32.tf32.f32 "
      "{%0,%1,%2,%3}, {%4,%5,%6,%7}, {%8,%9}, {%0,%1,%2,%3};"
      : "+f"(d[0]), "+f"(d[1]), "+f"(d[2]), "+f"(d[3])
      : "r"(a0), "r"(a1), "r"(a2), "r"(a3), "r"(b0), "r"(b1));
}

// ---------------------------------------------------------------------------
// Init kernel: tf32-convert + permute weights into k8-chunked N-major layout:
//   WBUF[off + kc*N*8 + n*8 + w] = tf32( W[(kc*8 + (w&1)*4 + (w>>1)) * N + n] )
// An LDG.64 at [n*8 + p*2] yields (k=kc*8+p, k=kc*8+p+4) = exactly the
// (b0,b1) fragment pair for mma.m16n8k8 lane p.
// ---------------------------------------------------------------------------
__global__ void prep_weights(const float* __restrict__ w1s,
                             const float* __restrict__ w1v1,
                             const float* __restrict__ w1v2,
                             const float* __restrict__ w2s,
                             const float* __restrict__ w2v1,
                             const float* __restrict__ w2v2)
{
  int idx = blockIdx.x * blockDim.x + threadIdx.x;
  if (idx >= WBUF_SZ) return;
  const float* src; int N, loc;
  if      (idx < W2S_OFF)  { src = w1s;  N = 448; loc = idx - W1S_OFF;  }
  else if (idx < W1V1_OFF) { src = w2s;  N = 256; loc = idx - W2S_OFF;  }
  else if (idx < W2V1_OFF) { src = w1v1; N = 128; loc = idx - W1V1_OFF; }
  else if (idx < W1V2_OFF) { src = w2v1; N = 128; loc = idx - W2V1_OFF; }
  else if (idx < W2V2_OFF) { src = w1v2; N = 64;  loc = idx - W1V2_OFF; }
  else                     { src = w2v2; N = 64;  loc = idx - W2V2_OFF; }
  int kc = loc / (N*8); int r = loc - kc*N*8; int n = r >> 3; int w = r & 7;
  int k = kc*8 + (w&1)*4 + (w>>1);
  WBUF[idx] = f2tff(src[k*N + n]);
}

// ---------------------------------------------------------------------------
// acc += A(SMEM tf32, pitch PA) @ B(WBUF k8-packed, via direct LDG.64),
// software-pipelined one k8-step ahead. NO barriers inside.
// ---------------------------------------------------------------------------
template<int K, int N, int WM, int WN, int PA>
static __device__ __forceinline__ void run_gemm(const float* __restrict__ gB,
                  const float* __restrict__ As, float* acc,
                  int lane, int mi, int nj)
{
  constexpr int NK8 = K/8;
  const float2* __restrict__ bbase =
      reinterpret_cast<const float2*>(gB) + (lane & 3);
  const float* ap0 = As + (mi*WM*16 + (lane>>2))*PA + (lane & 3);

  float2 bc[WN], bn[WN];
  #pragma unroll
  for (int wn=0; wn<WN; wn++){
    int col = (nj*WN+wn)*8 + (lane>>2);
    bc[wn] = __ldg(bbase + col*4);
  }
  #pragma unroll 2
  for (int kc=0; kc<NK8; kc++){
    if (kc+1 < NK8){
      #pragma unroll
      for (int wn=0; wn<WN; wn++){
        int col = (nj*WN+wn)*8 + (lane>>2);
        bn[wn] = __ldg(bbase + (kc+1)*(N*4) + col*4);
      }
    }
    uint32_t a[WM][4];
    #pragma unroll
    for (int wm=0; wm<WM; wm++){
      const float* ap = ap0 + wm*16*PA + kc*8;
      a[wm][0] = __float_as_uint(ap[0]);
      a[wm][1] = __float_as_uint(ap[8*PA]);
      a[wm][2] = __float_as_uint(ap[4]);
      a[wm][3] = __float_as_uint(ap[8*PA+4]);
    }
    #pragma unroll
    for (int wn=0; wn<WN; wn++){
      uint32_t b0 = __float_as_uint(bc[wn].x);
      uint32_t b1 = __float_as_uint(bc[wn].y);
      #pragma unroll
      for (int wm=0; wm<WM; wm++)
        mma8(acc+(wm*WN+wn)*4, a[wm][0],a[wm][1],a[wm][2],a[wm][3], b0, b1);
    }
    #pragma unroll
    for (int wn=0; wn<WN; wn++) bc[wn] = bn[wn];
  }
}

static __device__ __forceinline__ float sspf(float v, float cssp){
  float sp = fmaxf(v, 0.0f) + log1pf(expf(-fabsf(v)));
  return cssp * (sp - 0.69314718055994531f);
}

__global__ void __launch_bounds__(NT, 1)
resblk_kernel(const float* __restrict__ x, float* __restrict__ out, float cssp)
{
  extern __shared__ float sm[];
  float* seg1 = sm;
  float* G    = sm + G_OFF;

  const int tid  = threadIdx.x;
  const int lane = tid & 31;
  const int warp = tid >> 5;
  const int mi2  = warp & 1;      // 2M x 8N grid (scalar-path GEMMs)
  const int nj2  = warp >> 1;
  const int mi4  = warp >> 2;     // 4M x 4N grid (vector-path GEMMs)
  const int nj4  = warp & 3;
  const int n0   = blockIdx.x * TILE;
  const float RS128 = 0.08838834764831845f;
  const float RS64  = 0.125f;

  // ================= scalar path =================
  // A0 = tf32(x0 tile)  [64 x 256], pitch 260
  for (int t=tid; t<(TILE*256)/4; t+=NT){
    int e=t*4; int ln=e>>8; int col=e&255;
    float4 v = *reinterpret_cast<const float4*>(x + (size_t)(n0+ln)*960 + col);
    *reinterpret_cast<float4*>(seg1 + ln*260 + col) =
      make_float4(f2tff(v.x),f2tff(v.y),f2tff(v.z),f2tff(v.w));
  }
  __syncthreads();
  // s = A0 @ w1s / 16, SSP -> scalars(seg1, tf32) + gates(G, fp32)
  {
    float acc[56];
    #pragma unroll
    for (int i=0;i<56;i++) acc[i]=0.f;
    run_gemm<256,448,2,7,260>(&WBUF[W1S_OFF], seg1, acc, lane, mi2, nj2);
    __syncthreads();
    #pragma unroll
    for (int wm=0; wm<2; wm++){
      #pragma unroll
      for (int wn=0; wn<7; wn++){
        #pragma unroll
        for (int q=0;q<4;q++){
          int row = (mi2*2+wm)*16 + (lane>>2) + ((q&2)<<2);
          int col = (nj2*7+wn)*8 + ((lane&3)<<1) + (q&1);
          float h = sspf(acc[(wm*7+wn)*4+q]*0.0625f, cssp);
          if (col < 256) seg1[row*260 + col] = f2tff(h);
          else           G[row*196 + (col-256)] = h;
        }
      }
    }
  }
  __syncthreads();
  // y0 = scalars @ w2s / 16 ; stage then coalesced residual write
  {
    float acc[32];
    #pragma unroll
    for (int i=0;i<32;i++) acc[i]=0.f;
    run_gemm<256,256,2,4,260>(&WBUF[W2S_OFF], seg1, acc, lane, mi2, nj2);
    __syncthreads();
    #pragma unroll
    for (int wm=0; wm<2; wm++){
      #pragma unroll
      for (int wn=0; wn<4; wn++){
        #pragma unroll
        for (int q=0;q<4;q++){
          int row = (mi2*2+wm)*16 + (lane>>2) + ((q&2)<<2);
          int col = (nj2*4+wn)*8 + ((lane&3)<<1) + (q&1);
          seg1[row*260 + col] = acc[(wm*4+wn)*4+q]*0.0625f;
        }
      }
    }
    __syncthreads();
    for (int t=tid; t<TILE*64; t+=NT){
      int ln=t>>6; int j=(t&63)*4;
      size_t off = (size_t)(n0+ln)*960 + j;
      float4 xr = *reinterpret_cast<const float4*>(x + off);
      float4 yv = *reinterpret_cast<const float4*>(seg1 + ln*260 + j);
      *reinterpret_cast<float4*>(out + off) =
        make_float4(xr.x+yv.x, xr.y+yv.y, xr.z+yv.z, xr.w+yv.w);
    }
  }
  __syncthreads();

  // ================= v1 path =================
  // A1[c*64+n][i] = tf32(x[n, 256+3i+c])  [192 x 128], pitch 132
  for (int t=tid; t<(TILE*384)/4; t+=NT){
    int e=t*4; int ln=e/384; int j=e-ln*384;
    float4 v = *reinterpret_cast<const float4*>(x + (size_t)(n0+ln)*960 + 256 + j);
    float vv[4]={v.x,v.y,v.z,v.w};
    #pragma unroll
    for (int q=0;q<4;q++){
      int jj=j+q; int i3=jj/3; int c=jj-i3*3;
      seg1[(c*64+ln)*132 + i3] = f2tff(vv[q]);
    }
  }
  __syncthreads();
  // V1 = A1 @ w1v1 * rs128, gated, in place (tf32)
  {
    float acc[48];
    #pragma unroll
    for (int i=0;i<48;i++) acc[i]=0.f;
    run_gemm<128,128,3,4,132>(&WBUF[W1V1_OFF], seg1, acc, lane, mi4, nj4);
    __syncthreads();
    #pragma unroll
    for (int wm=0; wm<3; wm++){
      #pragma unroll
      for (int wn=0; wn<4; wn++){
        #pragma unroll
        for (int q=0;q<4;q++){
          int row = (mi4*3+wm)*16 + (lane>>2) + ((q&2)<<2);
          int col = (nj4*4+wn)*8 + ((lane&3)<<1) + (q&1);
          float g = G[(row&63)*196 + col];
          seg1[row*132 + col] = f2tff(acc[(wm*4+wn)*4+q]*RS128*g);
        }
      }
    }
  }
  __syncthreads();
  // Y1 = V1 @ w2v1 * rs128 -> stage [n][3o+c] -> coalesced residual write
  {
    float acc[48];
    #pragma unroll
    for (int i=0;i<48;i++) acc[i]=0.f;
    run_gemm<128,128,3,4,132>(&WBUF[W2V1_OFF], seg1, acc, lane, mi4, nj4);
    __syncthreads();
    #pragma unroll
    for (int wm=0; wm<3; wm++){
      #pragma unroll
      for (int wn=0; wn<4; wn++){
        #pragma unroll
        for (int q=0;q<4;q++){
          int row = (mi4*3+wm)*16 + (lane>>2) + ((q&2)<<2);
          int col = (nj4*4+wn)*8 + ((lane&3)<<1) + (q&1);
          int n = row & 63; int c = row >> 6;
          seg1[n*388 + 3*col + c] = acc[(wm*4+wn)*4+q]*RS128;
        }
      }
    }
    __syncthreads();
    for (int t=tid; t<TILE*96; t+=NT){
      int ln=t/96; int j=(t-ln*96)*4;
      size_t off = (size_t)(n0+ln)*960 + 256 + j;
      float4 xr = *reinterpret_cast<const float4*>(x + off);
      float4 yv = *reinterpret_cast<const float4*>(seg1 + ln*388 + j);
      *reinterpret_cast<float4*>(out + off) =
        make_float4(xr.x+yv.x, xr.y+yv.y, xr.z+yv.z, xr.w+yv.w);
    }
  }
  __syncthreads();

  // ================= v2 path =================
  // A2[c*64+n][i] = tf32(x[n, 640+5i+c])  [320 x 64], pitch 68
  for (int t=tid; t<(TILE*320)/4; t+=NT){
    int e=t*4; int ln=e/320; int j=e-ln*320;
    float4 v = *reinterpret_cast<const float4*>(x + (size_t)(n0+ln)*960 + 640 + j);
    float vv[4]={v.x,v.y,v.z,v.w};
    #pragma unroll
    for (int q=0;q<4;q++){
      int jj=j+q; int i5=jj/5; int c=jj-i5*5;
      seg1[(c*64+ln)*68 + i5] = f2tff(vv[q]);
    }
  }
  __syncthreads();
  // V2 = A2 @ w1v2 * rs64, gated, in place (tf32)
  {
    float acc[40];
    #pragma unroll
    for (int i=0;i<40;i++) acc[i]=0.f;
    run_gemm<64,64,5,2,68>(&WBUF[W1V2_OFF], seg1, acc, lane, mi4, nj4);
    __syncthreads();
    #pragma unroll
    for (int wm=0; wm<5; wm++){
      #pragma unroll
      for (int wn=0; wn<2; wn++){
        #pragma unroll
        for (int q=0;q<4;q++){
          int row = (mi4*5+wm)*16 + (lane>>2) + ((q&2)<<2);
          int col = (nj4*2+wn)*8 + ((lane&3)<<1) + (q&1);
          float g = G[(row&63)*196 + 128 + col];
          seg1[row*68 + col] = f2tff(acc[(wm*2+wn)*4+q]*RS64*g);
        }
      }
    }
  }
  __syncthreads();
  // Y2 = V2 @ w2v2 * rs64 -> stage [n][5o+c] -> coalesced residual write
  {
    float acc[40];
    #pragma unroll
    for (int i=0;i<40;i++) acc[i]=0.f;
    run_gemm<64,64,5,2,68>(&WBUF[W2V2_OFF], seg1, acc, lane, mi4, nj4);
    __syncthreads();
    #pragma unroll
    for (int wm=0; wm<5; wm++){
      #pragma unroll
      for (int wn=0; wn<2; wn++){
        #pragma unroll
        for (int q=0;q<4;q++){
          int row = (mi4*5+wm)*16 + (lane>>2) + ((q&2)<<2);
          int col = (nj4*2+wn)*8 + ((lane&3)<<1) + (q&1);
          int n = row & 63; int c = row >> 6;
          seg1[n*324 + 5*col + c] = acc[(wm*2+wn)*4+q]*RS64;
        }
      }
    }
    __syncthreads();
    for (int t=tid; t<TILE*80; t+=NT){
      int ln=t/80; int j=(t-ln*80)*4;
      size_t off = (size_t)(n0+ln)*960 + 640 + j;
      float4 xr = *reinterpret_cast<const float4*>(x + off);
      float4 yv = *reinterpret_cast<const float4*>(seg1 + ln*324 + j);
      *reinterpret_cast<float4*>(out + off) =
        make_float4(xr.x+yv.x, xr.y+yv.y, xr.z+yv.z, xr.w+yv.w);
    }
  }
}

static double compute_cssp_host(){
  const int NP = 200001;
  const double LOG2 = 0.6931471805599453094172321214581766;
  double s = 0.0;
  for (int i=0;i<NP;i++){
    double z = -10.0 + (20.0 * i) / (NP - 1);
    double phi = exp(-0.5*z*z) / sqrt(2.0*3.14159265358979323846);
    double sp  = (z > 0.0) ? (z + log1p(exp(-z))) : log1p(exp(z));
    double f   = sp - LOG2;
    double w   = (i==0 || i==NP-1) ? 0.5 : 1.0;
    s += w * f * f * phi;
  }
  s *= 20.0 / (NP - 1);
  return 1.0 / sqrt(s);
}

extern "C" void kernel_launch(void* const* d_in, const int* in_sizes, int n_in,
                              void* d_out, int out_size) {
  const float* x    = (const float*)d_in[0];
  const float* w1s  = (const float*)d_in[1];
  const float* w1v1 = (const float*)d_in[2];
  const float* w1v2 = (const float*)d_in[3];
  const float* w2s  = (const float*)d_in[4];
  const float* w2v1 = (const float*)d_in[5];
  const float* w2v2 = (const float*)d_in[6];
  float* out = (float*)d_out;

  int n = in_sizes[0] / 960;

  static bool attr_done = false;
  if (!attr_done){
    cudaFuncSetAttribute(resblk_kernel,
        cudaFuncAttributeMaxDynamicSharedMemorySize, SMEM_FLOATS*4);
    attr_done = true;
  }
  static const float cssp = (float)compute_cssp_host();

  prep_weights<<<(WBUF_SZ + NT - 1)/NT, NT>>>(w1s, w1v1, w1v2, w2s, w2v1, w2v2);
  resblk_kernel<<<n/TILE, NT, SMEM_FLOATS*4>>>(x, out, cssp);
}

// round 5
// speedup vs baseline: 1.3236x; 1.0407x over previous
#include <cuda_runtime.h>
#include <cstdint>
#include <math.h>

#define NT 512
#define TILE 64
#define G_OFF    25344        // seg1 size: 192*132 floats
#define SMEM_FLOATS 37888     // seg1 + G (64*196)  = 151552 bytes

// Pre-converted tf32 weights, permuted per-k8-chunk N-major (filled by prep_weights)
#define W1S_OFF   0
#define W2S_OFF   114688
#define W1V1_OFF  180224
#define W2V1_OFF  196608
#define W1V2_OFF  212992
#define W2V2_OFF  217088
#define WBUF_SZ   221184
__device__ float WBUF[WBUF_SZ];

static __device__ __forceinline__ float f2tff(float f){
  uint32_t u; asm("cvt.rna.tf32.f32 %0, %1;" : "=r"(u) : "f"(f));
  return __uint_as_float(u);
}

static __device__ __forceinline__ void mma8(float* d, uint32_t a0, uint32_t a1,
                                            uint32_t a2, uint32_t a3,
                                            uint32_t b0, uint32_t b1){
  asm volatile("mma.sync.aligned.m16n8k8.row.col.f32.tf32.tf32.f32 "
      "{%0,%1,%2,%3}, {%4,%5,%6,%7}, {%8,%9}, {%0,%1,%2,%3};"
      : "+f"(d[0]), "+f"(d[1]), "+f"(d[2]), "+f"(d[3])
      : "r"(a0), "r"(a1), "r"(a2), "r"(a3), "r"(b0), "r"(b1));
}

// One ldmatrix.x4 = the whole 16x8 tf32 A fragment (a0..a3) for one m16 tile.
static __device__ __forceinline__ void ldsm4(uint32_t* r, uint32_t addr){
  asm volatile("ldmatrix.sync.aligned.m8n8.x4.shared.b16 {%0,%1,%2,%3}, [%4];"
      : "=r"(r[0]), "=r"(r[1]), "=r"(r[2]), "=r"(r[3]) : "r"(addr));
}

// ---------------------------------------------------------------------------
// Init kernel: tf32-convert + permute weights into k8-chunked N-major layout:
//   WBUF[off + kc*N*8 + n*8 + w] = tf32( W[(kc*8 + (w&1)*4 + (w>>1)) * N + n] )
// LDG.64 at [n*8 + p*2] -> (b0,b1) for mma lane p of k8-chunk kc.
// ---------------------------------------------------------------------------
__global__ void prep_weights(const float* __restrict__ w1s,
                             const float* __restrict__ w1v1,
                             const float* __restrict__ w1v2,
                             const float* __restrict__ w2s,
                             const float* __restrict__ w2v1,
                             const float* __restrict__ w2v2)
{
  int idx = blockIdx.x * blockDim.x + threadIdx.x;
  if (idx >= WBUF_SZ) return;
  const float* src; int N, loc;
  if      (idx < W2S_OFF)  { src = w1s;  N = 448; loc = idx - W1S_OFF;  }
  else if (idx < W1V1_OFF) { src = w2s;  N = 256; loc = idx - W2S_OFF;  }
  else if (idx < W2V1_OFF) { src = w1v1; N = 128; loc = idx - W1V1_OFF; }
  else if (idx < W1V2_OFF) { src = w2v1; N = 128; loc = idx - W2V1_OFF; }
  else if (idx < W2V2_OFF) { src = w1v2; N = 64;  loc = idx - W1V2_OFF; }
  else                     { src = w2v2; N = 64;  loc = idx - W2V2_OFF; }
  int kc = loc / (N*8); int r = loc - kc*N*8; int n = r >> 3; int w = r & 7;
  int k = kc*8 + (w&1)*4 + (w>>1);
  WBUF[idx] = f2tff(src[k*N + n]);
}

// ---------------------------------------------------------------------------
// acc += A(SMEM tf32, pitch PA, via ldmatrix.x4) @ B(WBUF k8-packed, LDG.64),
// both operands software-pipelined one k8-step ahead. No barriers inside.
// ---------------------------------------------------------------------------
template<int K, int N, int WM, int WN, int PA>
static __device__ __forceinline__ void run_gemm(const float* __restrict__ gB,
                  uint32_t As_u32, float* acc, int lane, int mi, int nj)
{
  constexpr int NK8 = K/8;
  const float2* __restrict__ bp = reinterpret_cast<const float2*>(gB)
      + (lane & 3) + ((nj*WN)*8 + (lane>>2))*4;
  const int g = lane >> 3, r = lane & 7;
  const uint32_t aaddr = As_u32
      + ((uint32_t)(((mi*WM)*16 + r + (g&1)*8)*PA + (g>>1)*4))*4u;

  float2   b[2][WN];
  uint32_t a[2][WM][4];
  #pragma unroll
  for (int wn=0; wn<WN; wn++) b[0][wn] = __ldg(bp + wn*32);
  #pragma unroll
  for (int wm=0; wm<WM; wm++) ldsm4(a[0][wm], aaddr + wm*(16*PA*4));

  #pragma unroll 4
  for (int kc=0; kc<NK8; kc++){
    const int cur = kc & 1, nxt = cur ^ 1;
    if (kc+1 < NK8){
      #pragma unroll
      for (int wn=0; wn<WN; wn++) b[nxt][wn] = __ldg(bp + (kc+1)*(N*4) + wn*32);
      #pragma unroll
      for (int wm=0; wm<WM; wm++) ldsm4(a[nxt][wm], aaddr + wm*(16*PA*4) + (kc+1)*32);
    }
    #pragma unroll
    for (int wn=0; wn<WN; wn++){
      uint32_t b0 = __float_as_uint(b[cur][wn].x);
      uint32_t b1 = __float_as_uint(b[cur][wn].y);
      #pragma unroll
      for (int wm=0; wm<WM; wm++)
        mma8(acc+(wm*WN+wn)*4, a[cur][wm][0],a[cur][wm][1],a[cur][wm][2],a[cur][wm][3], b0, b1);
    }
  }
}

static __device__ __forceinline__ float sspf(float v, float cssp){
  float sp = fmaxf(v, 0.0f) + log1pf(expf(-fabsf(v)));
  return cssp * (sp - 0.69314718055994531f);
}

__global__ void __launch_bounds__(NT, 1)
resblk_kernel(const float* __restrict__ x, float* __restrict__ out, float cssp)
{
  extern __shared__ float sm[];
  float* seg1 = sm;
  float* G    = sm + G_OFF;
  uint32_t sm_u32;
  { uint32_t a; asm("{ .reg .u64 t; cvta.to.shared.u64 t, %1; cvt.u32.u64 %0, t; }"
                    : "=r"(a) : "l"(sm)); sm_u32 = a; }

  const int tid  = threadIdx.x;
  const int lane = tid & 31;
  const int warp = tid >> 5;
  const int mi2  = warp & 1;      // 2M x 8N grid (scalar-path GEMMs)
  const int nj2  = warp >> 1;
  const int mi4  = warp >> 2;     // 4M x 4N grid (vector-path GEMMs)
  const int nj4  = warp & 3;
  const int n0   = blockIdx.x * TILE;
  const float RS128 = 0.08838834764831845f;
  const float RS64  = 0.125f;

  // ================= scalar path =================
  // A0 = tf32(x0 tile)  [64 x 256], pitch 260
  for (int t=tid; t<(TILE*256)/4; t+=NT){
    int e=t*4; int ln=e>>8; int col=e&255;
    float4 v = *reinterpret_cast<const float4*>(x + (size_t)(n0+ln)*960 + col);
    *reinterpret_cast<float4*>(seg1 + ln*260 + col) =
      make_float4(f2tff(v.x),f2tff(v.y),f2tff(v.z),f2tff(v.w));
  }
  __syncthreads();
  // s = A0 @ w1s / 16, SSP -> scalars(seg1, tf32) + gates(G, fp32)
  {
    float acc[56];
    #pragma unroll
    for (int i=0;i<56;i++) acc[i]=0.f;
    run_gemm<256,448,2,7,260>(&WBUF[W1S_OFF], sm_u32, acc, lane, mi2, nj2);
    __syncthreads();
    #pragma unroll
    for (int wm=0; wm<2; wm++){
      #pragma unroll
      for (int wn=0; wn<7; wn++){
        #pragma unroll
        for (int q=0;q<4;q++){
          int row = (mi2*2+wm)*16 + (lane>>2) + ((q&2)<<2);
          int col = (nj2*7+wn)*8 + ((lane&3)<<1) + (q&1);
          float h = sspf(acc[(wm*7+wn)*4+q]*0.0625f, cssp);
          if (col < 256) seg1[row*260 + col] = f2tff(h);
          else           G[row*196 + (col-256)] = h;
        }
      }
    }
  }
  __syncthreads();
  // y0 = scalars @ w2s / 16 ; stage then coalesced residual write
  {
    float acc[32];
    #pragma unroll
    for (int i=0;i<32;i++) acc[i]=0.f;
    run_gemm<256,256,2,4,260>(&WBUF[W2S_OFF], sm_u32, acc, lane, mi2, nj2);
    __syncthreads();
    #pragma unroll
    for (int wm=0; wm<2; wm++){
      #pragma unroll
      for (int wn=0; wn<4; wn++){
        #pragma unroll
        for (int q=0;q<4;q++){
          int row = (mi2*2+wm)*16 + (lane>>2) + ((q&2)<<2);
          int col = (nj2*4+wn)*8 + ((lane&3)<<1) + (q&1);
          seg1[row*260 + col] = acc[(wm*4+wn)*4+q]*0.0625f;
        }
      }
    }
    __syncthreads();
    for (int t=tid; t<TILE*64; t+=NT){
      int ln=t>>6; int j=(t&63)*4;
      size_t off = (size_t)(n0+ln)*960 + j;
      float4 xr = *reinterpret_cast<const float4*>(x + off);
      float4 yv = *reinterpret_cast<const float4*>(seg1 + ln*260 + j);
      *reinterpret_cast<float4*>(out + off) =
        make_float4(xr.x+yv.x, xr.y+yv.y, xr.z+yv.z, xr.w+yv.w);
    }
  }
  __syncthreads();

  // ================= v1 path =================
  // A1[c*64+n][i] = tf32(x[n, 256+3i+c])  [192 x 128], pitch 132
  for (int t=tid; t<(TILE*384)/4; t+=NT){
    int e=t*4; int ln=e/384; int j=e-ln*384;
    float4 v = *reinterpret_cast<const float4*>(x + (size_t)(n0+ln)*960 + 256 + j);
    float vv[4]={v.x,v.y,v.z,v.w};
    #pragma unroll
    for (int q=0;q<4;q++){
      int jj=j+q; int i3=jj/3; int c=jj-i3*3;
      seg1[(c*64+ln)*132 + i3] = f2tff(vv[q]);
    }
  }
  __syncthreads();
  // V1 = A1 @ w1v1 * rs128, gated, in place (tf32)
  {
    float acc[48];
    #pragma unroll
    for (int i=0;i<48;i++) acc[i]=0.f;
    run_gemm<128,128,3,4,132>(&WBUF[W1V1_OFF], sm_u32, acc, lane, mi4, nj4);
    __syncthreads();
    #pragma unroll
    for (int wm=0; wm<3; wm++){
      #pragma unroll
      for (int wn=0; wn<4; wn++){
        #pragma unroll
        for (int q=0;q<4;q++){
          int row = (mi4*3+wm)*16 + (lane>>2) + ((q&2)<<2);
          int col = (nj4*4+wn)*8 + ((lane&3)<<1) + (q&1);
          float g = G[(row&63)*196 + col];
          seg1[row*132 + col] = f2tff(acc[(wm*4+wn)*4+q]*RS128*g);
        }
      }
    }
  }
  __syncthreads();
  // Y1 = V1 @ w2v1 * rs128 -> stage [n][3o+c] -> coalesced residual write
  {
    float acc[48];
    #pragma unroll
    for (int i=0;i<48;i++) acc[i]=0.f;
    run_gemm<128,128,3,4,132>(&WBUF[W2V1_OFF], sm_u32, acc, lane, mi4, nj4);
    __syncthreads();
    #pragma unroll
    for (int wm=0; wm<3; wm++){
      #pragma unroll
      for (int wn=0; wn<4; wn++){
        #pragma unroll
        for (int q=0;q<4;q++){
          int row = (mi4*3+wm)*16 + (lane>>2) + ((q&2)<<2);
          int col = (nj4*4+wn)*8 + ((lane&3)<<1) + (q&1);
          int n = row & 63; int c = row >> 6;
          seg1[n*388 + 3*col + c] = acc[(wm*4+wn)*4+q]*RS128;
        }
      }
    }
    __syncthreads();
    for (int t=tid; t<TILE*96; t+=NT){
      int ln=t/96; int j=(t-ln*96)*4;
      size_t off = (size_t)(n0+ln)*960 + 256 + j;
      float4 xr = *reinterpret_cast<const float4*>(x + off);
      float4 yv = *reinterpret_cast<const float4*>(seg1 + ln*388 + j);
      *reinterpret_cast<float4*>(out + off) =
        make_float4(xr.x+yv.x, xr.y+yv.y, xr.z+yv.z, xr.w+yv.w);
    }
  }
  __syncthreads();

  // ================= v2 path =================
  // A2[c*64+n][i] = tf32(x[n, 640+5i+c])  [320 x 64], pitch 68
  for (int t=tid; t<(TILE*320)/4; t+=NT){
    int e=t*4; int ln=e/320; int j=e-ln*320;
    float4 v = *reinterpret_cast<const float4*>(x + (size_t)(n0+ln)*960 + 640 + j);
    float vv[4]={v.x,v.y,v.z,v.w};
    #pragma unroll
    for (int q=0;q<4;q++){
      int jj=j+q; int i5=jj/5; int c=jj-i5*5;
      seg1[(c*64+ln)*68 + i5] = f2tff(vv[q]);
    }
  }
  __syncthreads();
  // V2 = A2 @ w1v2 * rs64, gated, in place (tf32)
  {
    float acc[40];
    #pragma unroll
    for (int i=0;i<40;i++) acc[i]=0.f;
    run_gemm<64,64,5,2,68>(&WBUF[W1V2_OFF], sm_u32, acc, lane, mi4, nj4);
    __syncthreads();
    #pragma unroll
    for (int wm=0; wm<5; wm++){
      #pragma unroll
      for (int wn=0; wn<2; wn++){
        #pragma unroll
        for (int q=0;q<4;q++){
          int row = (mi4*5+wm)*16 + (lane>>2) + ((q&2)<<2);
          int col = (nj4*2+wn)*8 + ((lane&3)<<1) + (q&1);
          float g = G[(row&63)*196 + 128 + col];
          seg1[row*68 + col] = f2tff(acc[(wm*2+wn)*4+q]*RS64*g);
        }
      }
    }
  }
  __syncthreads();
  // Y2 = V2 @ w2v2 * rs64 -> stage [n][5o+c] -> coalesced residual write
  {
    float acc[40];
    #pragma unroll
    for (int i=0;i<40;i++) acc[i]=0.f;
    run_gemm<64,64,5,2,68>(&WBUF[W2V2_OFF], sm_u32, acc, lane, mi4, nj4);
    __syncthreads();
    #pragma unroll
    for (int wm=0; wm<5; wm++){
      #pragma unroll
      for (int wn=0; wn<2; wn++){
        #pragma unroll
        for (int q=0;q<4;q++){
          int row = (mi4*5+wm)*16 + (lane>>2) + ((q&2)<<2);
          int col = (nj4*2+wn)*8 + ((lane&3)<<1) + (q&1);
          int n = row & 63; int c = row >> 6;
          seg1[n*324 + 5*col + c] = acc[(wm*2+wn)*4+q]*RS64;
        }
      }
    }
    __syncthreads();
    for (int t=tid; t<TILE*80; t+=NT){
      int ln=t/80; int j=(t-ln*80)*4;
      size_t off = (size_t)(n0+ln)*960 + 640 + j;
      float4 xr = *reinterpret_cast<const float4*>(x + off);
      float4 yv = *reinterpret_cast<const float4*>(seg1 + ln*324 + j);
      *reinterpret_cast<float4*>(out + off) =
        make_float4(xr.x+yv.x, xr.y+yv.y, xr.z+yv.z, xr.w+yv.w);
    }
  }
}

static double compute_cssp_host(){
  const int NP = 200001;
  const double LOG2 = 0.6931471805599453094172321214581766;
  double s = 0.0;
  for (int i=0;i<NP;i++){
    double z = -10.0 + (20.0 * i) / (NP - 1);
    double phi = exp(-0.5*z*z) / sqrt(2.0*3.14159265358979323846);
    double sp  = (z > 0.0) ? (z + log1p(exp(-z))) : log1p(exp(z));
    double f   = sp - LOG2;
    double w   = (i==0 || i==NP-1) ? 0.5 : 1.0;
    s += w * f * f * phi;
  }
  s *= 20.0 / (NP - 1);
  return 1.0 / sqrt(s);
}

extern "C" void kernel_launch(void* const* d_in, const int* in_sizes, int n_in,
                              void* d_out, int out_size) {
  const float* x    = (const float*)d_in[0];
  const float* w1s  = (const float*)d_in[1];
  const float* w1v1 = (const float*)d_in[2];
  const float* w1v2 = (const float*)d_in[3];
  const float* w2s  = (const float*)d_in[4];
  const float* w2v1 = (const float*)d_in[5];
  const float* w2v2 = (const float*)d_in[6];
  float* out = (float*)d_out;

  int n = in_sizes[0] / 960;

  static bool attr_done = false;
  if (!attr_done){
    cudaFuncSetAttribute(resblk_kernel,
        cudaFuncAttributeMaxDynamicSharedMemorySize, SMEM_FLOATS*4);
    attr_done = true;
  }
  static const float cssp = (float)compute_cssp_host();

  prep_weights<<<(WBUF_SZ + NT - 1)/NT, NT>>>(w1s, w1v1, w1v2, w2s, w2v1, w2v2);
  resblk_kernel<<<n/TILE, NT, SMEM_FLOATS*4>>>(x, out, cssp);
}